// round 16
// baseline (speedup 1.0000x reference)
#include <cuda_runtime.h>
#include <cuda_bf16.h>
#include <cstdint>

#define NN 512
#define MM 512
#define DD 16
#define BIGF 1e10f

// Diagonal-major distance scratch: ddiag[b][k-2][i-1] = ||x_b[i-1] - y_b[k-i-2]||^2
// Indexed ((b<<10) + (k-2))*512 + (i-1). 64*1024*512 floats = 134 MB.
__device__ float g_ddiag[64u * 1024u * 512u];

// ---------------- Kernel 1: distance precompute, diagonal-major ----------------
// grid (64 batches, 8 k-chunks of 128), 512 threads. Thread t owns x row t.
__global__ __launch_bounds__(512, 2)
void dist_kernel(const float* __restrict__ x,
                 const float* __restrict__ y) {
    __shared__ float2 ypk[DD/2][MM];
    __shared__ float  y2s[MM];

    const int b = blockIdx.x;
    const int t = threadIdx.x;

    // load y row t into paired shared + y^2
    const float4* yb4 = reinterpret_cast<const float4*>(y + (size_t)b * MM * DD + (size_t)t * DD);
    float ysum = 0.f;
    #pragma unroll
    for (int q = 0; q < 4; q++) {
        float4 v = yb4[q];
        ypk[2*q+0][t] = make_float2(v.x, v.y);
        ypk[2*q+1][t] = make_float2(v.z, v.w);
        ysum += v.x*v.x + v.y*v.y + v.z*v.z + v.w*v.w;
    }
    y2s[t] = ysum;

    // x row t in packed regs + x^2
    uint64_t xp[DD/2];
    const float4* xb4 = reinterpret_cast<const float4*>(x + (size_t)b * NN * DD + (size_t)t * DD);
    float x2 = 0.f;
    #pragma unroll
    for (int q = 0; q < 4; q++) {
        float4 v = xb4[q];
        asm("mov.b64 %0, {%1,%2};" : "=l"(xp[2*q+0]) : "f"(v.x), "f"(v.y));
        asm("mov.b64 %0, {%1,%2};" : "=l"(xp[2*q+1]) : "f"(v.z), "f"(v.w));
        x2 += v.x*v.x + v.y*v.y + v.z*v.z + v.w*v.w;
    }
    __syncthreads();

    const int kbase = 2 + (int)blockIdx.y * 128;
    float* gp = g_ddiag + ((size_t)((b << 10) + (kbase - 2)) << 9) + t;

    #pragma unroll 4
    for (int it = 0; it < 128; ++it) {
        const int k = kbase + it;
        if (k <= NN + MM) {
            int col = k - t - 2;                 // j-1
            col = min(max(col, 0), MM - 1);      // clamp (invalid cells never read)
            uint64_t acc = 0ull;
            #pragma unroll
            for (int d2i = 0; d2i < DD/2; d2i++) {
                uint64_t yv = *reinterpret_cast<const uint64_t*>(&ypk[d2i][col]);
                asm("fma.rn.f32x2 %0, %1, %2, %3;" : "=l"(acc) : "l"(xp[d2i]), "l"(yv), "l"(acc));
            }
            float lo, hi;
            asm("mov.b64 {%0,%1}, %2;" : "=f"(lo), "=f"(hi) : "l"(acc));
            const float dot = lo + hi;
            gp[0] = fmaf(-2.0f, dot, x2 + y2s[col]);
        }
        gp += 512;
    }
}

// ---------------- Kernel 2: wavefront DP over precomputed distances ----------------
// One CTA per batch, thread t owns DP row i = t+1. 3-deep LDG prefetch of diagonals.
__global__ __launch_bounds__(512, 1)
void softdtw_kernel(float* __restrict__ out) {
    __shared__ float dbuf[3][NN + 1];

    const int b = blockIdx.x;
    const int t = threadIdx.x;
    const int i = t + 1;

    dbuf[0][t+1] = BIGF; dbuf[1][t+1] = BIGF; dbuf[2][t+1] = BIGF;
    if (t == 0) { dbuf[0][0] = 0.0f; dbuf[1][0] = BIGF; dbuf[2][0] = BIGF; }
    __syncthreads();

    const float* gp = g_ddiag + ((size_t)(b << 10) << 9) + t;  // diag k=2, slot t
    // rolling prefetch: diagonals k, k+1, k+2
    float dcur = __ldg(gp);
    float dn1  = __ldg(gp + 512);
    float dn2  = __ldg(gp + 1024);
    gp += 1536;   // next load target: k+3

    float* d0 = dbuf[0];
    float* d1 = dbuf[1];
    float* d2 = dbuf[2];
    float myPrev = BIGF;

    for (int k = 2; k <= NN + MM; ++k) {
        float val = BIGF;
        const int j = k - i;
        if ((unsigned)(j - 1) < (unsigned)MM) {
            const float a  = d0[i-1];
            const float bb = d1[i-1];
            const float c  = myPrev;
            const float m = fminf(a, fminf(bb, c));
            const float s = __expf(m - a) + __expf(m - bb) + __expf(m - c);
            val = dcur + m - __logf(s);
        }
        // shift prefetch pipeline and issue next load (k+3)
        dcur = dn1; dn1 = dn2;
        if (k + 3 <= NN + MM) dn2 = __ldg(gp);
        gp += 512;

        d2[i] = val;
        if (t == 0) d2[0] = BIGF;
        myPrev = val;
        __syncthreads();
        float* tmp = d0; d0 = d1; d1 = d2; d2 = tmp;
    }

    if (i == NN) out[b] = myPrev;
}

extern "C" void kernel_launch(void* const* d_in, const int* in_sizes, int n_in,
                              void* d_out, int out_size) {
    const float* x = (const float*)d_in[0];
    const float* y = (const float*)d_in[1];
    float* out = (float*)d_out;
    dist_kernel<<<dim3(64, 8), 512>>>(x, y);
    softdtw_kernel<<<64, 512>>>(out);
}